// round 5
// baseline (speedup 1.0000x reference)
#include <cuda_runtime.h>
#include <stdint.h>

// ---------------------------------------------------------------------------
// GAT layer (PyG GATConv semantics, add_self_loops=True):
//   h = x @ W                       [N, H*OUT]
//   a_src[n,h] = <h[n,h,:], att_src[h,:]>,  a_dst likewise
//   per edge (j->i): alpha = leaky_relu(a_src[j]+a_dst[i])
//   softmax over incoming edges of i, weighted scatter of h[j], + bias
//
// Softmax computed WITHOUT the max-shift: exp(a)/sum(exp(a)) is algebraically
// identical to the shifted form; logits are Glorot-scaled dot products with
// |alpha| < ~8, far from fp32 overflow. Every node has a self-loop so every
// segment is non-empty (reference's isfinite fixup is a no-op).
//
// Passes (default stream, sequential):
//   0. detect : edge_index dtype sniff (int64 vs int32) -> g_is64
//   1. init   : out <- bias broadcast, denom <- 0
//   2. gemm   : h, a_src, a_dst   (W staged in 64KB smem, warp/row)
//   3. esum   : per-edge exp(leaky(alpha)), red.add.v4 into denom[dst]
//   4. recip  : denom <- 1/(denom + 1e-16)
//   5. escat  : warp/edge; lanes 0-3 compute the 4 head weights (1 expf each),
//               shfl-broadcast, red.global.add.v4.f32 of w*h[src] into out[dst]
// ---------------------------------------------------------------------------

#define NN        100000
#define FEAT      128      // H*OUT
#define HH        4
#define NEG_SLOPE 0.2f

// 16B alignment is REQUIRED: these are accessed as float4 / red.add.v4.
__device__ __align__(16) float g_h[(size_t)NN * FEAT];     // 51.2 MB
__device__ __align__(16) float g_asrc[(size_t)NN * HH];
__device__ __align__(16) float g_adst[(size_t)NN * HH];
__device__ __align__(16) float g_denom[(size_t)NN * HH];   // later: reciprocal
__device__ int g_is64;

__device__ __forceinline__ float leaky(float a) {
    return (a >= 0.f) ? a : NEG_SLOPE * a;
}

// ---------------------------------------------------------------------------
__global__ void detect_kernel(const void* ei) {
    // int64 indices in [0, N) have zero high words; int32 data read as u64
    // yields values >= 2^32 unless the paired index is 0 (prob ~1e-5 each).
    const unsigned long long* p = (const unsigned long long*)ei;
    int ok = 1;
    #pragma unroll
    for (int i = 0; i < 8; i++)
        if (p[i] >= (unsigned long long)NN) ok = 0;
    g_is64 = ok;
}

__global__ __launch_bounds__(256) void init_kernel(
        const float* __restrict__ bias, int n, float* __restrict__ out) {
    long long total = (long long)n * FEAT;
    for (long long i = (long long)blockIdx.x * blockDim.x + threadIdx.x;
         i < total; i += (long long)gridDim.x * blockDim.x) {
        out[i] = bias[(int)(i & (FEAT - 1))];
        if (i < (long long)n * HH) g_denom[i] = 0.0f;
    }
}

// ---------------------------------------------------------------------------
// GEMM + attention dots. 256 threads = 8 warps. One warp per row.
// Dynamic smem: W[128*128] (64KB) + per-warp x row buffers (8*128, 4KB).
__global__ __launch_bounds__(256, 3) void gemm_att_kernel(
        const float* __restrict__ x, const float* __restrict__ W,
        const float* __restrict__ att_src, const float* __restrict__ att_dst,
        int n) {
    extern __shared__ float sm[];
    float* Ws = sm;               // 128*128
    float* xs = sm + FEAT * FEAT; // 8 * 128
    __shared__ float s_as[FEAT], s_ad[FEAT];

    for (int i = threadIdx.x; i < FEAT * FEAT / 4; i += blockDim.x)
        ((float4*)Ws)[i] = ((const float4*)W)[i];
    if (threadIdx.x < FEAT) {
        s_as[threadIdx.x] = att_src[threadIdx.x];
        s_ad[threadIdx.x] = att_dst[threadIdx.x];
    }
    __syncthreads();

    const int warp = threadIdx.x >> 5;
    const int lane = threadIdx.x & 31;
    float* xw = xs + warp * FEAT;
    const long long gw = (long long)blockIdx.x * 8 + warp;
    const long long nw = (long long)gridDim.x * 8;

    for (long long row = gw; row < n; row += nw) {
        ((float4*)xw)[lane] = ((const float4*)(x + row * FEAT))[lane];
        __syncwarp();

        float a0 = 0.f, a1 = 0.f, a2 = 0.f, a3 = 0.f;
        #pragma unroll 8
        for (int k = 0; k < FEAT; k++) {
            const float  xv = xw[k];
            const float4 w4 = ((const float4*)(Ws + k * FEAT))[lane];
            a0 = fmaf(xv, w4.x, a0);
            a1 = fmaf(xv, w4.y, a1);
            a2 = fmaf(xv, w4.z, a2);
            a3 = fmaf(xv, w4.w, a3);
        }
        ((float4*)(g_h + row * FEAT))[lane] = make_float4(a0, a1, a2, a3);

        // lane covers channels [lane*4, lane*4+4); head = lane/8;
        // reduce partials over groups of 8 lanes.
        const int cb = lane * 4;
        float ps = a0 * s_as[cb] + a1 * s_as[cb + 1] + a2 * s_as[cb + 2] + a3 * s_as[cb + 3];
        float pd = a0 * s_ad[cb] + a1 * s_ad[cb + 1] + a2 * s_ad[cb + 2] + a3 * s_ad[cb + 3];
        #pragma unroll
        for (int off = 4; off >= 1; off >>= 1) {
            ps += __shfl_down_sync(0xffffffffu, ps, off, 8);
            pd += __shfl_down_sync(0xffffffffu, pd, off, 8);
        }
        if ((lane & 7) == 0) {
            const int head = lane >> 3;
            g_asrc[row * HH + head] = ps;
            g_adst[row * HH + head] = pd;
        }
        __syncwarp();   // protect xw reuse
    }
}

// ---------------------------------------------------------------------------
// Denominator pass: 1 thread per edge (grid-stride), all 4 heads vectorized.
__global__ __launch_bounds__(256) void edge_sum_kernel(
        const void* __restrict__ ei, long long E, int n) {
    const long long tot    = E + n;
    const long long stride = (long long)gridDim.x * blockDim.x;
    const int is64 = g_is64;

    for (long long e = (long long)blockIdx.x * blockDim.x + threadIdx.x;
         e < tot; e += stride) {
        int s, d;
        if (e < E) {
            if (is64) {
                s = (int)((const long long*)ei)[e];
                d = (int)((const long long*)ei)[E + e];
            } else {
                s = ((const int*)ei)[e];
                d = ((const int*)ei)[E + e];
            }
        } else { s = d = (int)(e - E); }

        const float4 as = ((const float4*)g_asrc)[s];
        const float4 ad = ((const float4*)g_adst)[d];
        float e0 = __expf(leaky(as.x + ad.x));
        float e1 = __expf(leaky(as.y + ad.y));
        float e2 = __expf(leaky(as.z + ad.z));
        float e3 = __expf(leaky(as.w + ad.w));
        float* dst = g_denom + (size_t)d * HH;
        asm volatile("red.global.add.v4.f32 [%0], {%1, %2, %3, %4};"
                     :: "l"(dst), "f"(e0), "f"(e1), "f"(e2), "f"(e3)
                     : "memory");
    }
}

__global__ __launch_bounds__(256) void recip_kernel(int n) {
    const long long tot = (long long)n * HH;
    const long long i = (long long)blockIdx.x * blockDim.x + threadIdx.x;
    if (i < tot) g_denom[i] = 1.0f / (g_denom[i] + 1e-16f);
}

// ---------------------------------------------------------------------------
// Scatter: one warp per edge (grid-stride over warps). Lanes 0-3 compute the
// 4 per-head weights (one __expf each, 4 instead of 32 per edge); a single
// shfl broadcasts to consumer lanes (head = lane/8). Lane handles 4
// contiguous channels. red.global.add.v4.f32 (no return).
__global__ __launch_bounds__(256) void edge_scatter_kernel(
        const void* __restrict__ ei, long long E, int n,
        float* __restrict__ out) {
    const long long tot     = E + n;
    const long long wstride = ((long long)gridDim.x * blockDim.x) >> 5;
    const int lane = threadIdx.x & 31;
    const int head = lane >> 3;
    const int is64 = g_is64;

    for (long long e = ((long long)blockIdx.x * blockDim.x + threadIdx.x) >> 5;
         e < tot; e += wstride) {
        int s, d;
        if (e < E) {
            if (is64) {
                s = (int)((const long long*)ei)[e];
                d = (int)((const long long*)ei)[E + e];
            } else {
                s = ((const int*)ei)[e];
                d = ((const int*)ei)[E + e];
            }
        } else { s = d = (int)(e - E); }

        float wv = 0.f;
        if (lane < HH) {
            const float a = leaky(__ldg(&g_asrc[(size_t)s * HH + lane]) +
                                  __ldg(&g_adst[(size_t)d * HH + lane]));
            wv = __expf(a) * __ldg(&g_denom[(size_t)d * HH + lane]);
        }
        const float w = __shfl_sync(0xffffffffu, wv, head);

        const float4 hv = ((const float4*)(g_h + (size_t)s * FEAT))[lane];
        float* dst = out + (size_t)d * FEAT + lane * 4;
        asm volatile("red.global.add.v4.f32 [%0], {%1, %2, %3, %4};"
                     :: "l"(dst), "f"(hv.x * w), "f"(hv.y * w),
                        "f"(hv.z * w), "f"(hv.w * w)
                     : "memory");
    }
}

// ---------------------------------------------------------------------------
extern "C" void kernel_launch(void* const* d_in, const int* in_sizes, int n_in,
                              void* d_out, int out_size) {
    const float* x       = (const float*)d_in[0];
    const void*  ei      = d_in[1];
    const float* W       = (const float*)d_in[2];
    const float* att_src = (const float*)d_in[3];
    const float* att_dst = (const float*)d_in[4];
    const float* bias    = (const float*)d_in[5];
    float* out = (float*)d_out;

    const int       n = in_sizes[0] / FEAT;         // 100000
    const long long E = (long long)in_sizes[1] / 2; // 1000000

    detect_kernel<<<1, 1>>>(ei);

    init_kernel<<<2048, 256>>>(bias, n, out);

    {
        const int smem = (FEAT * FEAT + 8 * FEAT) * (int)sizeof(float); // 69632
        cudaFuncSetAttribute(gemm_att_kernel,
                             cudaFuncAttributeMaxDynamicSharedMemorySize, smem);
        gemm_att_kernel<<<1024, 256, smem>>>(x, W, att_src, att_dst, n);
    }

    // persistent grid: full waves on 148+ SMs
    edge_sum_kernel<<<148 * 8, 256>>>(ei, E, n);

    {
        int threads = 256;
        long long blocks = ((long long)n * HH + threads - 1) / threads;
        recip_kernel<<<(unsigned)blocks, threads>>>(n);
    }

    // warp per edge, persistent: 148*64 blocks * 8 warps ≈ 75K warps
    edge_scatter_kernel<<<148 * 64, 256>>>(ei, E, n, out);
}

// round 8
// speedup vs baseline: 1.4611x; 1.4611x over previous
#include <cuda_runtime.h>
#include <stdint.h>

// ---------------------------------------------------------------------------
// GAT layer (PyG GATConv semantics, add_self_loops=True).
// Passes: detect -> init -> gemm (4-row-blocked, f32x2 packed FMA) ->
//         esum -> recip -> escat.
// Softmax computed without max-shift (algebraically identical; logits bounded).
// ---------------------------------------------------------------------------

#define NN        100000
#define FEAT      128      // H*OUT
#define HH        4
#define NEG_SLOPE 0.2f
#define RPB       4        // rows per warp in GEMM

// 16B alignment REQUIRED: accessed as float4 / ulonglong2 / red.add.v4.
__device__ __align__(16) float g_h[(size_t)NN * FEAT];     // 51.2 MB
__device__ __align__(16) float g_asrc[(size_t)NN * HH];
__device__ __align__(16) float g_adst[(size_t)NN * HH];
__device__ __align__(16) float g_denom[(size_t)NN * HH];   // later: reciprocal
__device__ int g_is64;

__device__ __forceinline__ float leaky(float a) {
    return (a >= 0.f) ? a : NEG_SLOPE * a;
}

// ---- packed f32x2 helpers (Blackwell FFMA2 path, PTX-only) ----
__device__ __forceinline__ unsigned long long pack2(float a, float b) {
    unsigned long long r;
    asm("mov.b64 %0, {%1, %2};" : "=l"(r) : "f"(a), "f"(b));
    return r;
}
__device__ __forceinline__ unsigned long long ffma2(
        unsigned long long a, unsigned long long b, unsigned long long c) {
    unsigned long long d;
    asm("fma.rn.f32x2 %0, %1, %2, %3;" : "=l"(d) : "l"(a), "l"(b), "l"(c));
    return d;
}
__device__ __forceinline__ float2 unpack2(unsigned long long v) {
    float2 f;
    asm("mov.b64 {%0, %1}, %2;" : "=f"(f.x), "=f"(f.y) : "l"(v));
    return f;
}

// ---------------------------------------------------------------------------
__global__ void detect_kernel(const void* ei) {
    const unsigned long long* p = (const unsigned long long*)ei;
    int ok = 1;
    #pragma unroll
    for (int i = 0; i < 8; i++)
        if (p[i] >= (unsigned long long)NN) ok = 0;
    g_is64 = ok;
}

__global__ __launch_bounds__(256) void init_kernel(
        const float* __restrict__ bias, int n, float* __restrict__ out) {
    long long total = (long long)n * FEAT;
    for (long long i = (long long)blockIdx.x * blockDim.x + threadIdx.x;
         i < total; i += (long long)gridDim.x * blockDim.x) {
        out[i] = bias[(int)(i & (FEAT - 1))];
        if (i < (long long)n * HH) g_denom[i] = 0.0f;
    }
}

// ---------------------------------------------------------------------------
// GEMM + attention dots. 8 warps/block, RPB=4 rows per warp per iteration.
// W staged in smem (64KB), read once per 4 rows (ulonglong2 = 2 f32x2 ops).
// Dynamic smem: W (64KB) + x rows (8*4*128 floats = 16KB) = 80KB.
__global__ __launch_bounds__(256, 2) void gemm_att_kernel(
        const float* __restrict__ x, const float* __restrict__ W,
        const float* __restrict__ att_src, const float* __restrict__ att_dst,
        int n) {
    extern __shared__ float sm[];
    float* Ws = sm;                      // FEAT*FEAT
    float* xs = sm + FEAT * FEAT;        // 8 * RPB * FEAT
    __shared__ float s_as[FEAT], s_ad[FEAT];

    for (int i = threadIdx.x; i < FEAT * FEAT / 4; i += blockDim.x)
        ((float4*)Ws)[i] = ((const float4*)W)[i];
    if (threadIdx.x < FEAT) {
        s_as[threadIdx.x] = att_src[threadIdx.x];
        s_ad[threadIdx.x] = att_dst[threadIdx.x];
    }
    __syncthreads();

    const int warp = threadIdx.x >> 5;
    const int lane = threadIdx.x & 31;
    float* xw = xs + warp * (RPB * FEAT);
    const ulonglong2* Ws2 = (const ulonglong2*)Ws;   // [k][lane] 16B granules

    const long long base = ((long long)blockIdx.x * 8 + warp) * RPB;
    const long long step = (long long)gridDim.x * 8 * RPB;

    for (long long row0 = base; row0 < n; row0 += step) {
        const int nr = (int)((n - row0 < RPB) ? (n - row0) : RPB);
        #pragma unroll
        for (int r = 0; r < RPB; r++)
            if (r < nr)
                ((float4*)(xw + r * FEAT))[lane] =
                    ((const float4*)(x + (row0 + r) * FEAT))[lane];
        __syncwarp();

        // acc[r][0] = cols (lane*4+0, lane*4+1); acc[r][1] = (+2, +3)
        unsigned long long acc[RPB][2];
        #pragma unroll
        for (int r = 0; r < RPB; r++) { acc[r][0] = 0ull; acc[r][1] = 0ull; }

        for (int k = 0; k < FEAT; k += 4) {
            float4 xv[RPB];
            #pragma unroll
            for (int r = 0; r < RPB; r++)
                xv[r] = *((const float4*)(xw + r * FEAT + k));   // broadcast
            #pragma unroll
            for (int kk = 0; kk < 4; kk++) {
                const ulonglong2 w2 = Ws2[(k + kk) * (FEAT / 4) + lane];
                #pragma unroll
                for (int r = 0; r < RPB; r++) {
                    const float xr = (kk == 0) ? xv[r].x :
                                     (kk == 1) ? xv[r].y :
                                     (kk == 2) ? xv[r].z : xv[r].w;
                    const unsigned long long xx = pack2(xr, xr);
                    acc[r][0] = ffma2(xx, w2.x, acc[r][0]);
                    acc[r][1] = ffma2(xx, w2.y, acc[r][1]);
                }
            }
        }

        #pragma unroll
        for (int r = 0; r < RPB; r++) {
            if (r >= nr) break;
            const float2 lo = unpack2(acc[r][0]);
            const float2 hi = unpack2(acc[r][1]);
            const long long row = row0 + r;
            ((float4*)(g_h + row * FEAT))[lane] =
                make_float4(lo.x, lo.y, hi.x, hi.y);

            // attention dots: lane covers channels [lane*4, +4); head=lane/8;
            // reduce partials over 8-lane groups.
            const int cb = lane * 4;
            float ps = lo.x * s_as[cb] + lo.y * s_as[cb + 1] +
                       hi.x * s_as[cb + 2] + hi.y * s_as[cb + 3];
            float pd = lo.x * s_ad[cb] + lo.y * s_ad[cb + 1] +
                       hi.x * s_ad[cb + 2] + hi.y * s_ad[cb + 3];
            #pragma unroll
            for (int off = 4; off >= 1; off >>= 1) {
                ps += __shfl_down_sync(0xffffffffu, ps, off, 8);
                pd += __shfl_down_sync(0xffffffffu, pd, off, 8);
            }
            if ((lane & 7) == 0) {
                const int head = lane >> 3;
                g_asrc[row * HH + head] = ps;
                g_adst[row * HH + head] = pd;
            }
        }
        __syncwarp();   // protect xw reuse
    }
}

// ---------------------------------------------------------------------------
// Denominator pass: 1 thread per edge (grid-stride), all 4 heads vectorized.
__global__ __launch_bounds__(256) void edge_sum_kernel(
        const void* __restrict__ ei, long long E, int n) {
    const long long tot    = E + n;
    const long long stride = (long long)gridDim.x * blockDim.x;
    const int is64 = g_is64;

    for (long long e = (long long)blockIdx.x * blockDim.x + threadIdx.x;
         e < tot; e += stride) {
        int s, d;
        if (e < E) {
            if (is64) {
                s = (int)((const long long*)ei)[e];
                d = (int)((const long long*)ei)[E + e];
            } else {
                s = ((const int*)ei)[e];
                d = ((const int*)ei)[E + e];
            }
        } else { s = d = (int)(e - E); }

        const float4 as = ((const float4*)g_asrc)[s];
        const float4 ad = ((const float4*)g_adst)[d];
        float e0 = __expf(leaky(as.x + ad.x));
        float e1 = __expf(leaky(as.y + ad.y));
        float e2 = __expf(leaky(as.z + ad.z));
        float e3 = __expf(leaky(as.w + ad.w));
        float* dst = g_denom + (size_t)d * HH;
        asm volatile("red.global.add.v4.f32 [%0], {%1, %2, %3, %4};"
                     :: "l"(dst), "f"(e0), "f"(e1), "f"(e2), "f"(e3)
                     : "memory");
    }
}

__global__ __launch_bounds__(256) void recip_kernel(int n) {
    const long long tot = (long long)n * HH;
    const long long i = (long long)blockIdx.x * blockDim.x + threadIdx.x;
    if (i < tot) g_denom[i] = 1.0f / (g_denom[i] + 1e-16f);
}

// ---------------------------------------------------------------------------
// Scatter: one warp per edge (grid-stride over warps). Lanes 0-3 compute the
// 4 per-head weights (4 expf/edge instead of 32); shfl-broadcast; lane handles
// 4 contiguous channels. red.global.add.v4.f32 (no return).
__global__ __launch_bounds__(256) void edge_scatter_kernel(
        const void* __restrict__ ei, long long E, int n,
        float* __restrict__ out) {
    const long long tot     = E + n;
    const long long wstride = ((long long)gridDim.x * blockDim.x) >> 5;
    const int lane = threadIdx.x & 31;
    const int head = lane >> 3;
    const int is64 = g_is64;

    for (long long e = ((long long)blockIdx.x * blockDim.x + threadIdx.x) >> 5;
         e < tot; e += wstride) {
        int s, d;
        if (e < E) {
            if (is64) {
                s = (int)((const long long*)ei)[e];
                d = (int)((const long long*)ei)[E + e];
            } else {
                s = ((const int*)ei)[e];
                d = ((const int*)ei)[E + e];
            }
        } else { s = d = (int)(e - E); }

        float wv = 0.f;
        if (lane < HH) {
            const float a = leaky(__ldg(&g_asrc[(size_t)s * HH + lane]) +
                                  __ldg(&g_adst[(size_t)d * HH + lane]));
            wv = __expf(a) * __ldg(&g_denom[(size_t)d * HH + lane]);
        }
        const float w = __shfl_sync(0xffffffffu, wv, head);

        const float4 hv = ((const float4*)(g_h + (size_t)s * FEAT))[lane];
        float* dst = out + (size_t)d * FEAT + lane * 4;
        asm volatile("red.global.add.v4.f32 [%0], {%1, %2, %3, %4};"
                     :: "l"(dst), "f"(hv.x * w), "f"(hv.y * w),
                        "f"(hv.z * w), "f"(hv.w * w)
                     : "memory");
    }
}

// ---------------------------------------------------------------------------
extern "C" void kernel_launch(void* const* d_in, const int* in_sizes, int n_in,
                              void* d_out, int out_size) {
    const float* x       = (const float*)d_in[0];
    const void*  ei      = d_in[1];
    const float* W       = (const float*)d_in[2];
    const float* att_src = (const float*)d_in[3];
    const float* att_dst = (const float*)d_in[4];
    const float* bias    = (const float*)d_in[5];
    float* out = (float*)d_out;

    const int       n = in_sizes[0] / FEAT;         // 100000
    const long long E = (long long)in_sizes[1] / 2; // 1000000

    detect_kernel<<<1, 1>>>(ei);

    init_kernel<<<2048, 256>>>(bias, n, out);

    {
        const int smem = (FEAT * FEAT + 8 * RPB * FEAT) * (int)sizeof(float); // 81920
        cudaFuncSetAttribute(gemm_att_kernel,
                             cudaFuncAttributeMaxDynamicSharedMemorySize, smem);
        gemm_att_kernel<<<296, 256, smem>>>(x, W, att_src, att_dst, n);
    }

    edge_sum_kernel<<<148 * 8, 256>>>(ei, E, n);

    {
        int threads = 256;
        long long blocks = ((long long)n * HH + threads - 1) / threads;
        recip_kernel<<<(unsigned)blocks, threads>>>(n);
    }

    edge_scatter_kernel<<<148 * 64, 256>>>(ei, E, n, out);
}